// round 12
// baseline (speedup 1.0000x reference)
#include <cuda_runtime.h>
#include <cuda_bf16.h>
#include <cuda_fp16.h>
#include <cstdint>

#define DIM   768
#define NH    12
#define HD    64
#define BATCH 8
#define SEQ   1024
#define M_TOT (BATCH * SEQ)   // 8192
#define QKV_N (3 * DIM)       // 2304

// Scratch (no allocation allowed in kernel_launch)
static __device__ float g_qkv[(size_t)M_TOT * QKV_N];
static __device__ __half g_xh[(size_t)M_TOT * DIM];
static __device__ __half g_xl[(size_t)M_TOT * DIM];
static __device__ __half g_qwh[(size_t)QKV_N * DIM];
static __device__ __half g_qwl[(size_t)QKV_N * DIM];
static __device__ __half g_pwh[(size_t)DIM * DIM];
static __device__ __half g_pwl[(size_t)DIM * DIM];
static __device__ __half g_ah[(size_t)M_TOT * DIM];
static __device__ __half g_al[(size_t)M_TOT * DIM];

// ---------------------------------------------------------------------------
// helpers
// ---------------------------------------------------------------------------
__device__ __forceinline__ uint32_t smem_u32(const void* p) {
    uint32_t a;
    asm("{ .reg .u64 t; cvta.to.shared.u64 t, %1; cvt.u32.u64 %0, t; }"
        : "=r"(a) : "l"(p));
    return a;
}
// bf16 split (attention-internal)
__device__ __forceinline__ void split1(float v, __nv_bfloat16& h, __nv_bfloat16& l) {
    h = __float2bfloat16(v);
    l = __float2bfloat16(v - __bfloat162float(h));
}
__device__ __forceinline__ uint32_t pack2(__nv_bfloat16 a, __nv_bfloat16 b) {
    return (uint32_t)__bfloat16_as_ushort(a) |
           ((uint32_t)__bfloat16_as_ushort(b) << 16);
}
__device__ __forceinline__ void split_pair(float a, float b,
                                           uint32_t& hi, uint32_t& lo) {
    __nv_bfloat16 ha, la, hb, lb;
    split1(a, ha, la); split1(b, hb, lb);
    hi = pack2(ha, hb); lo = pack2(la, lb);
}
// fp16 split (GEMM path)
__device__ __forceinline__ void split1h(float v, __half& h, __half& l) {
    h = __float2half(v);
    l = __float2half(v - __half2float(h));
}
__device__ __forceinline__ uint32_t pack2h(__half a, __half b) {
    return (uint32_t)__half_as_ushort(a) |
           ((uint32_t)__half_as_ushort(b) << 16);
}
__device__ __forceinline__ void split_pair_h(float a, float b,
                                             uint32_t& hi, uint32_t& lo) {
    __half ha, la, hb, lb;
    split1h(a, ha, la); split1h(b, hb, lb);
    hi = pack2h(ha, hb); lo = pack2h(la, lb);
}

#define LDX4(r, addr)                                                        \
    asm volatile("ldmatrix.sync.aligned.m8n8.x4.shared.b16 {%0,%1,%2,%3}, [%4];" \
        : "=r"((r)[0]), "=r"((r)[1]), "=r"((r)[2]), "=r"((r)[3])             \
        : "r"(addr))

#define LDX4T(r, addr)                                                       \
    asm volatile("ldmatrix.sync.aligned.m8n8.x4.trans.shared.b16 {%0,%1,%2,%3}, [%4];" \
        : "=r"((r)[0]), "=r"((r)[1]), "=r"((r)[2]), "=r"((r)[3])             \
        : "r"(addr))

// bf16 x bf16 -> f32 acc (attention)
#define MMA_BF16(c, a, b0, b1)                                               \
    asm volatile("mma.sync.aligned.m16n8k16.row.col.f32.bf16.bf16.f32 "      \
        "{%0,%1,%2,%3},{%4,%5,%6,%7},{%8,%9},{%0,%1,%2,%3};"                 \
        : "+f"((c)[0]), "+f"((c)[1]), "+f"((c)[2]), "+f"((c)[3])             \
        : "r"((a)[0]), "r"((a)[1]), "r"((a)[2]), "r"((a)[3]),                \
          "r"(b0), "r"(b1))

// f16 x f16 -> f32 acc (GEMM main term)
#define MMA_F16F32(c, a, b0, b1)                                             \
    asm volatile("mma.sync.aligned.m16n8k16.row.col.f32.f16.f16.f32 "        \
        "{%0,%1,%2,%3},{%4,%5,%6,%7},{%8,%9},{%0,%1,%2,%3};"                 \
        : "+f"((c)[0]), "+f"((c)[1]), "+f"((c)[2]), "+f"((c)[3])             \
        : "r"((a)[0]), "r"((a)[1]), "r"((a)[2]), "r"((a)[3]),                \
          "r"(b0), "r"(b1))

// f16 x f16 -> f16 acc (GEMM correction terms; c = 2 packed regs)
#define MMA_F16F16(c, a, b0, b1)                                             \
    asm volatile("mma.sync.aligned.m16n8k16.row.col.f16.f16.f16.f16 "        \
        "{%0,%1},{%2,%3,%4,%5},{%6,%7},{%0,%1};"                             \
        : "+r"((c)[0]), "+r"((c)[1])                                         \
        : "r"((a)[0]), "r"((a)[1]), "r"((a)[2]), "r"((a)[3]),                \
          "r"(b0), "r"(b1))

#define CP16(dst, src)                                                       \
    asm volatile("cp.async.ca.shared.global [%0], [%1], 16;"                 \
        :: "r"((uint32_t)(dst)), "l"(src))
#define CP_COMMIT()  asm volatile("cp.async.commit_group;" ::: "memory")
#define CP_WAIT(n)   asm volatile("cp.async.wait_group %0;" :: "n"(n) : "memory")

// ---------------------------------------------------------------------------
// f32 -> (hi, lo) fp16 split
// ---------------------------------------------------------------------------
__global__ void split_kernel(const float* __restrict__ in,
                             __half* __restrict__ h,
                             __half* __restrict__ l, int n)
{
    int i = (blockIdx.x * blockDim.x + threadIdx.x) * 4;
    if (i >= n) return;
    float4 v = *(const float4*)(in + i);
    uint32_t h0, l0, h1, l1;
    split_pair_h(v.x, v.y, h0, l0);
    split_pair_h(v.z, v.w, h1, l1);
    *(uint2*)(h + i) = make_uint2(h0, h1);
    *(uint2*)(l + i) = make_uint2(l0, l1);
}

// ---------------------------------------------------------------------------
// fp16 3-term GEMM, mixed accumulators:
//   D = f32acc(Ah*Bh) + f16acc(Ah*Bl + Al*Bh)
// 128x128 CTA, 256 thr, 8 warps of 64x32, cp.async double-buffered.
// ---------------------------------------------------------------------------
#define SB 40
#define ARR_B (128 * SB * 2)
#define BUF_B (4 * ARR_B)
#define GEMM_SMEM (2 * BUF_B)

__global__ __launch_bounds__(256) void gemm_f16mix(
    const __half* __restrict__ Ah, const __half* __restrict__ Al,
    const __half* __restrict__ Bh, const __half* __restrict__ Bl,
    const float* __restrict__ bias, float* __restrict__ C, int N, int K)
{
    extern __shared__ __align__(16) char smraw[];
    const uint32_t sbase = smem_u32(smraw);

    const int tid  = threadIdx.x;
    const int wid  = tid >> 5;
    const int lane = tid & 31;
    const int wm   = wid & 1;
    const int wn   = wid >> 1;
    const int bm   = blockIdx.y * 128;
    const int bn   = blockIdx.x * 128;

    const uint32_t offA = (uint32_t)(lane & 15) * (SB * 2) + ((lane & 16) ? 16 : 0);
    const uint32_t offB = (uint32_t)(((lane & 16) >> 1) + (lane & 7)) * (SB * 2)
                        + ((lane & 8) ? 16 : 0);

    const int lrow = tid >> 1;
    const int cb   = (tid & 1) * 16;
    const __half* pAh = Ah + (size_t)(bm + lrow) * K + cb;
    const __half* pAl = Al + (size_t)(bm + lrow) * K + cb;
    const __half* pBh = Bh + (size_t)(bn + lrow) * K + cb;
    const __half* pBl = Bl + (size_t)(bn + lrow) * K + cb;
    const uint32_t drow = (uint32_t)lrow * (SB * 2) + cb * 2;

    float acc[4][4][4];
    uint32_t cor[4][4][2];
#pragma unroll
    for (int t = 0; t < 4; t++)
#pragma unroll
        for (int u = 0; u < 4; u++) {
#pragma unroll
            for (int j = 0; j < 4; j++) acc[t][u][j] = 0.f;
            cor[t][u][0] = 0u; cor[t][u][1] = 0u;
        }

    const int nit = K / 32;

    auto issue = [&](int c) {
        const uint32_t ab = sbase + (uint32_t)((c & 1) * BUF_B) + drow;
        const int k0 = c * 32;
#pragma unroll
        for (int p = 0; p < 2; p++) {
            CP16(ab + p * 16,             pAh + k0 + p * 8);
            CP16(ab + ARR_B + p * 16,     pAl + k0 + p * 8);
            CP16(ab + 2 * ARR_B + p * 16, pBh + k0 + p * 8);
            CP16(ab + 3 * ARR_B + p * 16, pBl + k0 + p * 8);
        }
        CP_COMMIT();
    };

    issue(0);

    for (int c = 0; c < nit; c++) {
        if (c + 1 < nit) { issue(c + 1); CP_WAIT(1); }
        else             { CP_WAIT(0); }
        __syncthreads();

        const uint32_t ab  = sbase + (uint32_t)((c & 1) * BUF_B);
        const uint32_t uAh = ab;
        const uint32_t uAl = ab + ARR_B;
        const uint32_t uBh = ab + 2 * ARR_B;
        const uint32_t uBl = ab + 3 * ARR_B;

#pragma unroll
        for (int kk = 0; kk < 32; kk += 16) {
            uint32_t ah[4][4], al[4][4], bh[2][4], bl[2][4];
#pragma unroll
            for (int t = 0; t < 4; t++) {
                uint32_t base = (uint32_t)((wm * 64 + t * 16) * (SB * 2)) + kk * 2;
                LDX4(ah[t], uAh + base + offA);
                LDX4(al[t], uAl + base + offA);
            }
#pragma unroll
            for (int p = 0; p < 2; p++) {
                uint32_t base = (uint32_t)((wn * 32 + p * 16) * (SB * 2)) + kk * 2;
                LDX4(bh[p], uBh + base + offB);
                LDX4(bl[p], uBl + base + offB);
            }
#pragma unroll
            for (int t = 0; t < 4; t++) {
#pragma unroll
                for (int u = 0; u < 4; u++) {
                    const int p = u >> 1, o = (u & 1) * 2;
                    MMA_F16F32(acc[t][u], ah[t], bh[p][o], bh[p][o + 1]);
                    MMA_F16F16(cor[t][u], ah[t], bl[p][o], bl[p][o + 1]);
                    MMA_F16F16(cor[t][u], al[t], bh[p][o], bh[p][o + 1]);
                }
            }
        }
        __syncthreads();
    }

    const int er = lane >> 2;
    const int ec = (lane & 3) * 2;
#pragma unroll
    for (int t = 0; t < 4; t++) {
        const int row = bm + wm * 64 + t * 16 + er;
#pragma unroll
        for (int u = 0; u < 4; u++) {
            const int col = bn + wn * 32 + u * 8 + ec;
            const float b0 = bias[col], b1 = bias[col + 1];
            float2 c0 = __half22float2(*(__half2*)&cor[t][u][0]);
            float2 c1 = __half22float2(*(__half2*)&cor[t][u][1]);
            float2 v0 = {acc[t][u][0] + c0.x + b0, acc[t][u][1] + c0.y + b1};
            float2 v1 = {acc[t][u][2] + c1.x + b0, acc[t][u][3] + c1.y + b1};
            *(float2*)&C[(size_t)row * N + col]       = v0;
            *(float2*)&C[(size_t)(row + 8) * N + col] = v1;
        }
    }
}

// ---------------------------------------------------------------------------
// Tensor-core flash attention (round-8 core; epilogue emits fp16 hi/lo)
// ---------------------------------------------------------------------------
#define KSTR 72
#define ASZ  (64 * KSTR * 2)
#define BUFSZ (4 * ASZ)
#define ATTN_SMEM (2 * BUFSZ)

__global__ __launch_bounds__(128) void attn_mma(const float* __restrict__ qkv,
                                                __half* __restrict__ oh,
                                                __half* __restrict__ ol)
{
    extern __shared__ __align__(16) char smraw[];
    const uint32_t sb = smem_u32(smraw);

    const int tid  = threadIdx.x;
    const int w    = tid >> 5;
    const int lane = tid & 31;
    const int qt   = blockIdx.x * 64;
    const int b    = blockIdx.y / NH;
    const int h    = blockIdx.y % NH;

    const float* base = qkv + (size_t)b * SEQ * QKV_N + h * HD;

    const uint32_t offA = (uint32_t)(lane & 15) * (KSTR * 2) + ((lane & 16) ? 16 : 0);
    const uint32_t offB = (uint32_t)(((lane & 16) >> 1) + (lane & 7)) * (KSTR * 2)
                        + ((lane & 8) ? 16 : 0);

    const int lr = tid >> 1;
    const int lc = (tid & 1) * 32;
    const uint32_t stoff = (uint32_t)lr * (KSTR * 2) + lc * 2;

    {
        const float* qp = base + (size_t)(qt + lr) * QKV_N + lc;
#pragma unroll
        for (int j = 0; j < 8; j++) {
            float4 v = *(const float4*)(qp + j * 4);
            uint32_t h0, l0, h1, l1;
            split_pair(v.x * 0.125f, v.y * 0.125f, h0, l0);
            split_pair(v.z * 0.125f, v.w * 0.125f, h1, l1);
            *(uint2*)(smraw + stoff + j * 8)       = make_uint2(h0, h1);
            *(uint2*)(smraw + ASZ + stoff + j * 8) = make_uint2(l0, l1);
        }
    }
    __syncthreads();

    uint32_t qh[4][4], ql[4][4];
#pragma unroll
    for (int ks = 0; ks < 4; ks++) {
        uint32_t a = (uint32_t)(w * 16) * (KSTR * 2) + ks * 32 + offA;
        LDX4(qh[ks], sb + a);
        LDX4(ql[ks], sb + ASZ + a);
    }
    __syncthreads();

    const float* kbase = base + DIM + (size_t)lr * QKV_N + lc;
    float4 rk[8], rv[8];
#pragma unroll
    for (int j = 0; j < 8; j++) {
        rk[j] = *(const float4*)(kbase + j * 4);
        rv[j] = *(const float4*)(kbase + DIM + j * 4);
    }

    auto stage = [&](int buf) {
        char* p = smraw + buf * BUFSZ + stoff;
#pragma unroll
        for (int j = 0; j < 8; j++) {
            uint32_t h0, lo0, h1, lo1;
            split_pair(rk[j].x, rk[j].y, h0, lo0);
            split_pair(rk[j].z, rk[j].w, h1, lo1);
            *(uint2*)(p + j * 8)           = make_uint2(h0, h1);
            *(uint2*)(p + ASZ + j * 8)     = make_uint2(lo0, lo1);
            split_pair(rv[j].x, rv[j].y, h0, lo0);
            split_pair(rv[j].z, rv[j].w, h1, lo1);
            *(uint2*)(p + 2 * ASZ + j * 8) = make_uint2(h0, h1);
            *(uint2*)(p + 3 * ASZ + j * 8) = make_uint2(lo0, lo1);
        }
    };

    stage(0);
#pragma unroll
    for (int j = 0; j < 8; j++) {
        rk[j] = *(const float4*)(kbase + 64 * QKV_N + j * 4);
        rv[j] = *(const float4*)(kbase + 64 * QKV_N + DIM + j * 4);
    }
    __syncthreads();

    float oacc[8][4];
#pragma unroll
    for (int u = 0; u < 8; u++)
#pragma unroll
        for (int j = 0; j < 4; j++) oacc[u][j] = 0.f;
    float m0 = -1e30f, m1 = -1e30f, l0 = 0.f, l1 = 0.f;

    const int NT = SEQ / 64;
    for (int kt = 0; kt < NT; kt++) {
        const uint32_t bb  = sb + (uint32_t)((kt & 1) * BUFSZ);
        const uint32_t uKh = bb, uKl = bb + ASZ;
        const uint32_t uVh = bb + 2 * ASZ, uVl = bb + 3 * ASZ;

        float sacc[8][4];
#pragma unroll
        for (int u = 0; u < 8; u++)
#pragma unroll
            for (int j = 0; j < 4; j++) sacc[u][j] = 0.f;

#pragma unroll
        for (int ks = 0; ks < 4; ks++) {
#pragma unroll
            for (int np = 0; np < 4; np++) {
                uint32_t kh[4], kl[4];
                uint32_t a = (uint32_t)(np * 16) * (KSTR * 2) + ks * 32 + offB;
                LDX4(kh, uKh + a);
                LDX4(kl, uKl + a);
                const int u = np * 2;
                MMA_BF16(sacc[u],     qh[ks], kh[0], kh[1]);
                MMA_BF16(sacc[u],     qh[ks], kl[0], kl[1]);
                MMA_BF16(sacc[u],     ql[ks], kh[0], kh[1]);
                MMA_BF16(sacc[u + 1], qh[ks], kh[2], kh[3]);
                MMA_BF16(sacc[u + 1], qh[ks], kl[2], kl[3]);
                MMA_BF16(sacc[u + 1], ql[ks], kh[2], kh[3]);
            }
        }

        float mt0 = -1e30f, mt1 = -1e30f;
#pragma unroll
        for (int u = 0; u < 8; u++) {
            mt0 = fmaxf(mt0, fmaxf(sacc[u][0], sacc[u][1]));
            mt1 = fmaxf(mt1, fmaxf(sacc[u][2], sacc[u][3]));
        }
        mt0 = fmaxf(mt0, __shfl_xor_sync(0xffffffffu, mt0, 1));
        mt0 = fmaxf(mt0, __shfl_xor_sync(0xffffffffu, mt0, 2));
        mt1 = fmaxf(mt1, __shfl_xor_sync(0xffffffffu, mt1, 1));
        mt1 = fmaxf(mt1, __shfl_xor_sync(0xffffffffu, mt1, 2));

        const float mn0 = fmaxf(m0, mt0);
        const float mn1 = fmaxf(m1, mt1);
        const float a0 = __expf(m0 - mn0);
        const float a1 = __expf(m1 - mn1);

        float ls0 = 0.f, ls1 = 0.f;
#pragma unroll
        for (int u = 0; u < 8; u++) {
            sacc[u][0] = __expf(sacc[u][0] - mn0);
            sacc[u][1] = __expf(sacc[u][1] - mn0);
            sacc[u][2] = __expf(sacc[u][2] - mn1);
            sacc[u][3] = __expf(sacc[u][3] - mn1);
            ls0 += sacc[u][0] + sacc[u][1];
            ls1 += sacc[u][2] + sacc[u][3];
        }
        ls0 += __shfl_xor_sync(0xffffffffu, ls0, 1);
        ls0 += __shfl_xor_sync(0xffffffffu, ls0, 2);
        ls1 += __shfl_xor_sync(0xffffffffu, ls1, 1);
        ls1 += __shfl_xor_sync(0xffffffffu, ls1, 2);
        l0 = l0 * a0 + ls0;  m0 = mn0;
        l1 = l1 * a1 + ls1;  m1 = mn1;

#pragma unroll
        for (int u = 0; u < 8; u++) {
            oacc[u][0] *= a0; oacc[u][1] *= a0;
            oacc[u][2] *= a1; oacc[u][3] *= a1;
        }

        if (kt + 1 < NT) {
            stage((kt + 1) & 1);
            if (kt + 2 < NT) {
                const float* np = kbase + (size_t)(kt + 2) * 64 * QKV_N;
#pragma unroll
                for (int j = 0; j < 8; j++) {
                    rk[j] = *(const float4*)(np + j * 4);
                    rv[j] = *(const float4*)(np + DIM + j * 4);
                }
            }
        }

        uint32_t pah[4][4], pal[4][4];
#pragma unroll
        for (int t = 0; t < 4; t++) {
            split_pair(sacc[2 * t][0],     sacc[2 * t][1],     pah[t][0], pal[t][0]);
            split_pair(sacc[2 * t][2],     sacc[2 * t][3],     pah[t][1], pal[t][1]);
            split_pair(sacc[2 * t + 1][0], sacc[2 * t + 1][1], pah[t][2], pal[t][2]);
            split_pair(sacc[2 * t + 1][2], sacc[2 * t + 1][3], pah[t][3], pal[t][3]);
        }

#pragma unroll
        for (int t = 0; t < 4; t++) {
#pragma unroll
            for (int nd = 0; nd < 4; nd++) {
                uint32_t vh[4], vl[4];
                uint32_t a = (uint32_t)(t * 16) * (KSTR * 2) + nd * 32 + offB;
                LDX4T(vh, uVh + a);
                LDX4T(vl, uVl + a);
                const int u = nd * 2;
                MMA_BF16(oacc[u],     pah[t], vh[0], vh[2]);
                MMA_BF16(oacc[u],     pah[t], vl[0], vl[2]);
                MMA_BF16(oacc[u],     pal[t], vh[0], vh[2]);
                MMA_BF16(oacc[u + 1], pah[t], vh[1], vh[3]);
                MMA_BF16(oacc[u + 1], pah[t], vl[1], vl[3]);
                MMA_BF16(oacc[u + 1], pal[t], vh[1], vh[3]);
            }
        }
        __syncthreads();
    }

    // epilogue -> fp16 hi/lo for proj GEMM
    const float inv0 = 1.f / l0;
    const float inv1 = 1.f / l1;
    const int er = lane >> 2;
    const int ec = (lane & 3) * 2;
    const size_t tok0 = (size_t)b * SEQ + qt + w * 16 + er;
    const int colb = h * HD + ec;
#pragma unroll
    for (int u = 0; u < 8; u++) {
        const int col = colb + u * 8;
        uint32_t hp, lp;
        split_pair_h(oacc[u][0] * inv0, oacc[u][1] * inv0, hp, lp);
        *(uint32_t*)(oh + tok0 * DIM + col) = hp;
        *(uint32_t*)(ol + tok0 * DIM + col) = lp;
        split_pair_h(oacc[u][2] * inv1, oacc[u][3] * inv1, hp, lp);
        *(uint32_t*)(oh + (tok0 + 8) * DIM + col) = hp;
        *(uint32_t*)(ol + (tok0 + 8) * DIM + col) = lp;
    }
}

extern "C" void kernel_launch(void* const* d_in, const int* in_sizes, int n_in,
                              void* d_out, int out_size)
{
    const float* x      = (const float*)d_in[0];
    const float* qkv_w  = (const float*)d_in[1];
    const float* qkv_b  = (const float*)d_in[2];
    const float* proj_w = (const float*)d_in[3];
    const float* proj_b = (const float*)d_in[4];
    float* out = (float*)d_out;

    float* qkv;
    __half *xh, *xl, *qwh, *qwl, *pwh, *pwl, *ah, *al;
    cudaGetSymbolAddress((void**)&qkv, g_qkv);
    cudaGetSymbolAddress((void**)&xh,  g_xh);
    cudaGetSymbolAddress((void**)&xl,  g_xl);
    cudaGetSymbolAddress((void**)&qwh, g_qwh);
    cudaGetSymbolAddress((void**)&qwl, g_qwl);
    cudaGetSymbolAddress((void**)&pwh, g_pwh);
    cudaGetSymbolAddress((void**)&pwl, g_pwl);
    cudaGetSymbolAddress((void**)&ah,  g_ah);
    cudaGetSymbolAddress((void**)&al,  g_al);

    cudaFuncSetAttribute(gemm_f16mix,
                         cudaFuncAttributeMaxDynamicSharedMemorySize, GEMM_SMEM);
    cudaFuncSetAttribute(attn_mma,
                         cudaFuncAttributeMaxDynamicSharedMemorySize, ATTN_SMEM);

    // splits
    const int nx = M_TOT * DIM, nqw = QKV_N * DIM, npw = DIM * DIM;
    split_kernel<<<(nx / 4 + 255) / 256, 256>>>(x, xh, xl, nx);
    split_kernel<<<(nqw / 4 + 255) / 256, 256>>>(qkv_w, qwh, qwl, nqw);
    split_kernel<<<(npw / 4 + 255) / 256, 256>>>(proj_w, pwh, pwl, npw);

    // QKV projection: [8192, 2304]
    gemm_f16mix<<<dim3(QKV_N / 128, M_TOT / 128), 256, GEMM_SMEM>>>(
        xh, xl, qwh, qwl, qkv_b, qkv, QKV_N, DIM);

    // Attention (tensor-core, pipelined) -> fp16 hi/lo
    attn_mma<<<dim3(SEQ / 64, BATCH * NH), 128, ATTN_SMEM>>>(qkv, ah, al);

    // Output projection: [8192, 768]
    gemm_f16mix<<<dim3(DIM / 128, M_TOT / 128), 256, GEMM_SMEM>>>(
        ah, al, pwh, pwl, proj_b, out, DIM, DIM);
}

// round 13
// speedup vs baseline: 1.2107x; 1.2107x over previous
#include <cuda_runtime.h>
#include <cuda_bf16.h>
#include <cuda_fp16.h>
#include <cstdint>

#define DIM   768
#define NH    12
#define HD    64
#define BATCH 8
#define SEQ   1024
#define M_TOT (BATCH * SEQ)   // 8192
#define QKV_N (3 * DIM)       // 2304

// Scratch (no allocation allowed in kernel_launch)
static __device__ float g_qkv[(size_t)M_TOT * QKV_N];
static __device__ __nv_bfloat16 g_xh[(size_t)M_TOT * DIM];
static __device__ __nv_bfloat16 g_xl[(size_t)M_TOT * DIM];
static __device__ __nv_bfloat16 g_qwh[(size_t)QKV_N * DIM];
static __device__ __nv_bfloat16 g_qwl[(size_t)QKV_N * DIM];
static __device__ __nv_bfloat16 g_pwh[(size_t)DIM * DIM];
static __device__ __nv_bfloat16 g_pwl[(size_t)DIM * DIM];
static __device__ __nv_bfloat16 g_ah[(size_t)M_TOT * DIM];
static __device__ __nv_bfloat16 g_al[(size_t)M_TOT * DIM];

// ---------------------------------------------------------------------------
// helpers
// ---------------------------------------------------------------------------
__device__ __forceinline__ uint32_t smem_u32(const void* p) {
    uint32_t a;
    asm("{ .reg .u64 t; cvta.to.shared.u64 t, %1; cvt.u32.u64 %0, t; }"
        : "=r"(a) : "l"(p));
    return a;
}
// bf16 split (GEMM path)
__device__ __forceinline__ void split1(float v, __nv_bfloat16& h, __nv_bfloat16& l) {
    h = __float2bfloat16(v);
    l = __float2bfloat16(v - __bfloat162float(h));
}
__device__ __forceinline__ uint32_t pack2(__nv_bfloat16 a, __nv_bfloat16 b) {
    return (uint32_t)__bfloat16_as_ushort(a) |
           ((uint32_t)__bfloat16_as_ushort(b) << 16);
}
__device__ __forceinline__ void split_pair(float a, float b,
                                           uint32_t& hi, uint32_t& lo) {
    __nv_bfloat16 ha, la, hb, lb;
    split1(a, ha, la); split1(b, hb, lb);
    hi = pack2(ha, hb); lo = pack2(la, lb);
}
// fp16 pack (attention path, single-term)
__device__ __forceinline__ uint32_t pack2h(float a, float b) {
    __half2 h = __floats2half2_rn(a, b);
    return *(uint32_t*)&h;
}

#define LDX4(r, addr)                                                        \
    asm volatile("ldmatrix.sync.aligned.m8n8.x4.shared.b16 {%0,%1,%2,%3}, [%4];" \
        : "=r"((r)[0]), "=r"((r)[1]), "=r"((r)[2]), "=r"((r)[3])             \
        : "r"(addr))

#define LDX4T(r, addr)                                                       \
    asm volatile("ldmatrix.sync.aligned.m8n8.x4.trans.shared.b16 {%0,%1,%2,%3}, [%4];" \
        : "=r"((r)[0]), "=r"((r)[1]), "=r"((r)[2]), "=r"((r)[3])             \
        : "r"(addr))

#define MMA_BF16(c, a, b0, b1)                                               \
    asm volatile("mma.sync.aligned.m16n8k16.row.col.f32.bf16.bf16.f32 "      \
        "{%0,%1,%2,%3},{%4,%5,%6,%7},{%8,%9},{%0,%1,%2,%3};"                 \
        : "+f"((c)[0]), "+f"((c)[1]), "+f"((c)[2]), "+f"((c)[3])             \
        : "r"((a)[0]), "r"((a)[1]), "r"((a)[2]), "r"((a)[3]),                \
          "r"(b0), "r"(b1))

#define MMA_F16F32(c, a, b0, b1)                                             \
    asm volatile("mma.sync.aligned.m16n8k16.row.col.f32.f16.f16.f32 "        \
        "{%0,%1,%2,%3},{%4,%5,%6,%7},{%8,%9},{%0,%1,%2,%3};"                 \
        : "+f"((c)[0]), "+f"((c)[1]), "+f"((c)[2]), "+f"((c)[3])             \
        : "r"((a)[0]), "r"((a)[1]), "r"((a)[2]), "r"((a)[3]),                \
          "r"(b0), "r"(b1))

#define CP16(dst, src)                                                       \
    asm volatile("cp.async.ca.shared.global [%0], [%1], 16;"                 \
        :: "r"((uint32_t)(dst)), "l"(src))
#define CP_COMMIT()  asm volatile("cp.async.commit_group;" ::: "memory")
#define CP_WAIT(n)   asm volatile("cp.async.wait_group %0;" :: "n"(n) : "memory")

// ---------------------------------------------------------------------------
// f32 -> (hi, lo) bf16 split
// ---------------------------------------------------------------------------
__global__ void split_kernel(const float* __restrict__ in,
                             __nv_bfloat16* __restrict__ h,
                             __nv_bfloat16* __restrict__ l, int n)
{
    int i = (blockIdx.x * blockDim.x + threadIdx.x) * 4;
    if (i >= n) return;
    float4 v = *(const float4*)(in + i);
    uint32_t h0, l0, h1, l1;
    split_pair(v.x, v.y, h0, l0);
    split_pair(v.z, v.w, h1, l1);
    *(uint2*)(h + i) = make_uint2(h0, h1);
    *(uint2*)(l + i) = make_uint2(l0, l1);
}

// ---------------------------------------------------------------------------
// bf16 3-term GEMM (round-11 version, best measured: 278us, 2 CTA/SM)
// ---------------------------------------------------------------------------
#define SB 40
#define ARR_B (128 * SB * 2)
#define BUF_B (4 * ARR_B)
#define GEMM_SMEM (2 * BUF_B)

__global__ __launch_bounds__(256, 2) void gemm_bf16x3(
    const __nv_bfloat16* __restrict__ Ah, const __nv_bfloat16* __restrict__ Al,
    const __nv_bfloat16* __restrict__ Bh, const __nv_bfloat16* __restrict__ Bl,
    const float* __restrict__ bias, float* __restrict__ C, int N, int K)
{
    extern __shared__ __align__(16) char smraw[];
    const uint32_t sbase = smem_u32(smraw);

    const int tid  = threadIdx.x;
    const int wid  = tid >> 5;
    const int lane = tid & 31;
    const int wm   = wid & 1;
    const int wn   = wid >> 1;
    const int bm   = blockIdx.y * 128;
    const int bn   = blockIdx.x * 128;

    const uint32_t offA = (uint32_t)(lane & 15) * (SB * 2) + ((lane & 16) ? 16 : 0);
    const uint32_t offB = (uint32_t)(((lane & 16) >> 1) + (lane & 7)) * (SB * 2)
                        + ((lane & 8) ? 16 : 0);

    const int lrow = tid >> 1;
    const int cb   = (tid & 1) * 16;
    const __nv_bfloat16* pAh = Ah + (size_t)(bm + lrow) * K + cb;
    const __nv_bfloat16* pAl = Al + (size_t)(bm + lrow) * K + cb;
    const __nv_bfloat16* pBh = Bh + (size_t)(bn + lrow) * K + cb;
    const __nv_bfloat16* pBl = Bl + (size_t)(bn + lrow) * K + cb;
    const uint32_t drow = (uint32_t)lrow * (SB * 2) + cb * 2;

    float acc[4][4][4];
#pragma unroll
    for (int t = 0; t < 4; t++)
#pragma unroll
        for (int u = 0; u < 4; u++)
#pragma unroll
            for (int j = 0; j < 4; j++) acc[t][u][j] = 0.f;

    const int nit = K / 32;

    auto issue = [&](int c) {
        const uint32_t ab = sbase + (uint32_t)((c & 1) * BUF_B) + drow;
        const int k0 = c * 32;
#pragma unroll
        for (int p = 0; p < 2; p++) {
            CP16(ab + p * 16,             pAh + k0 + p * 8);
            CP16(ab + ARR_B + p * 16,     pAl + k0 + p * 8);
            CP16(ab + 2 * ARR_B + p * 16, pBh + k0 + p * 8);
            CP16(ab + 3 * ARR_B + p * 16, pBl + k0 + p * 8);
        }
        CP_COMMIT();
    };

    issue(0);

    for (int c = 0; c < nit; c++) {
        if (c + 1 < nit) { issue(c + 1); CP_WAIT(1); }
        else             { CP_WAIT(0); }
        __syncthreads();

        const uint32_t ab  = sbase + (uint32_t)((c & 1) * BUF_B);
        const uint32_t uAh = ab;
        const uint32_t uAl = ab + ARR_B;
        const uint32_t uBh = ab + 2 * ARR_B;
        const uint32_t uBl = ab + 3 * ARR_B;

#pragma unroll
        for (int kk = 0; kk < 32; kk += 16) {
            uint32_t ah[4][4], al[4][4], bh[2][4], bl[2][4];
#pragma unroll
            for (int t = 0; t < 4; t++) {
                uint32_t base = (uint32_t)((wm * 64 + t * 16) * (SB * 2)) + kk * 2;
                LDX4(ah[t], uAh + base + offA);
                LDX4(al[t], uAl + base + offA);
            }
#pragma unroll
            for (int p = 0; p < 2; p++) {
                uint32_t base = (uint32_t)((wn * 32 + p * 16) * (SB * 2)) + kk * 2;
                LDX4(bh[p], uBh + base + offB);
                LDX4(bl[p], uBl + base + offB);
            }
#pragma unroll
            for (int t = 0; t < 4; t++) {
#pragma unroll
                for (int u = 0; u < 4; u++) {
                    const int p = u >> 1, o = (u & 1) * 2;
                    MMA_BF16(acc[t][u], ah[t], bh[p][o], bh[p][o + 1]);
                    MMA_BF16(acc[t][u], ah[t], bl[p][o], bl[p][o + 1]);
                    MMA_BF16(acc[t][u], al[t], bh[p][o], bh[p][o + 1]);
                }
            }
        }
        __syncthreads();
    }

    const int er = lane >> 2;
    const int ec = (lane & 3) * 2;
#pragma unroll
    for (int t = 0; t < 4; t++) {
        const int row = bm + wm * 64 + t * 16 + er;
#pragma unroll
        for (int u = 0; u < 4; u++) {
            const int col = bn + wn * 32 + u * 8 + ec;
            const float b0 = bias[col], b1 = bias[col + 1];
            float2 v0 = {acc[t][u][0] + b0, acc[t][u][1] + b1};
            float2 v1 = {acc[t][u][2] + b0, acc[t][u][3] + b1};
            *(float2*)&C[(size_t)row * N + col]       = v0;
            *(float2*)&C[(size_t)(row + 8) * N + col] = v1;
        }
    }
}

// ---------------------------------------------------------------------------
// Tensor-core flash attention v5: SINGLE-TERM fp16 MMA for both QK^T and PV.
// 128 thr, 64 q-rows/CTA, double-buffered K/V fp16 smem + register prefetch.
// ---------------------------------------------------------------------------
#define KSTR 72
#define ASZ  (64 * KSTR * 2)      // 9216 bytes per array (fp16 64x64 + pad)
#define BUFSZ (2 * ASZ)           // K, V = 18432
#define ATTN_SMEM (2 * BUFSZ)     // 36864

__global__ __launch_bounds__(128) void attn_mma(const float* __restrict__ qkv,
                                                __nv_bfloat16* __restrict__ oh,
                                                __nv_bfloat16* __restrict__ ol)
{
    extern __shared__ __align__(16) char smraw[];
    const uint32_t sb = smem_u32(smraw);

    const int tid  = threadIdx.x;
    const int w    = tid >> 5;
    const int lane = tid & 31;
    const int qt   = blockIdx.x * 64;
    const int b    = blockIdx.y / NH;
    const int h    = blockIdx.y % NH;

    const float* base = qkv + (size_t)b * SEQ * QKV_N + h * HD;

    const uint32_t offA = (uint32_t)(lane & 15) * (KSTR * 2) + ((lane & 16) ? 16 : 0);
    const uint32_t offB = (uint32_t)(((lane & 16) >> 1) + (lane & 7)) * (KSTR * 2)
                        + ((lane & 8) ? 16 : 0);

    // loader mapping: row = tid/2, 32-col half
    const int lr = tid >> 1;
    const int lc = (tid & 1) * 32;
    const uint32_t stoff = (uint32_t)lr * (KSTR * 2) + lc * 2;   // byte offset

    // ---- stage Q (scaled fp16) into buf0 K region; pull A-frags ----
    {
        const float* qp = base + (size_t)(qt + lr) * QKV_N + lc;
#pragma unroll
        for (int j = 0; j < 8; j++) {
            float4 v = *(const float4*)(qp + j * 4);
            *(uint2*)(smraw + stoff + j * 8) =
                make_uint2(pack2h(v.x * 0.125f, v.y * 0.125f),
                           pack2h(v.z * 0.125f, v.w * 0.125f));
        }
    }
    __syncthreads();

    uint32_t qf[4][4];
#pragma unroll
    for (int ks = 0; ks < 4; ks++) {
        uint32_t a = (uint32_t)(w * 16) * (KSTR * 2) + ks * 32 + offA;
        LDX4(qf[ks], sb + a);
    }
    __syncthreads();

    // ---- prefetch tile 0 regs, stage, prefetch tile 1 ----
    const float* kbase = base + DIM + (size_t)lr * QKV_N + lc;
    float4 rk[8], rv[8];
#pragma unroll
    for (int j = 0; j < 8; j++) {
        rk[j] = *(const float4*)(kbase + j * 4);
        rv[j] = *(const float4*)(kbase + DIM + j * 4);
    }

    auto stage = [&](int buf) {
        char* p = smraw + buf * BUFSZ + stoff;
#pragma unroll
        for (int j = 0; j < 8; j++) {
            *(uint2*)(p + j * 8) =
                make_uint2(pack2h(rk[j].x, rk[j].y), pack2h(rk[j].z, rk[j].w));
            *(uint2*)(p + ASZ + j * 8) =
                make_uint2(pack2h(rv[j].x, rv[j].y), pack2h(rv[j].z, rv[j].w));
        }
    };

    stage(0);
#pragma unroll
    for (int j = 0; j < 8; j++) {
        rk[j] = *(const float4*)(kbase + 64 * QKV_N + j * 4);
        rv[j] = *(const float4*)(kbase + 64 * QKV_N + DIM + j * 4);
    }
    __syncthreads();

    float oacc[8][4];
#pragma unroll
    for (int u = 0; u < 8; u++)
#pragma unroll
        for (int j = 0; j < 4; j++) oacc[u][j] = 0.f;
    float m0 = -1e30f, m1 = -1e30f, l0 = 0.f, l1 = 0.f;

    const int NT = SEQ / 64;
    for (int kt = 0; kt < NT; kt++) {
        const uint32_t bb = sb + (uint32_t)((kt & 1) * BUFSZ);
        const uint32_t uK = bb;
        const uint32_t uV = bb + ASZ;

        // ---- S = Q @ K^T (single fp16 MMA per fragment) ----
        float sacc[8][4];
#pragma unroll
        for (int u = 0; u < 8; u++)
#pragma unroll
            for (int j = 0; j < 4; j++) sacc[u][j] = 0.f;

#pragma unroll
        for (int ks = 0; ks < 4; ks++) {
#pragma unroll
            for (int np = 0; np < 4; np++) {
                uint32_t kf[4];
                uint32_t a = (uint32_t)(np * 16) * (KSTR * 2) + ks * 32 + offB;
                LDX4(kf, uK + a);
                const int u = np * 2;
                MMA_F16F32(sacc[u],     qf[ks], kf[0], kf[1]);
                MMA_F16F32(sacc[u + 1], qf[ks], kf[2], kf[3]);
            }
        }

        // ---- online softmax ----
        float mt0 = -1e30f, mt1 = -1e30f;
#pragma unroll
        for (int u = 0; u < 8; u++) {
            mt0 = fmaxf(mt0, fmaxf(sacc[u][0], sacc[u][1]));
            mt1 = fmaxf(mt1, fmaxf(sacc[u][2], sacc[u][3]));
        }
        mt0 = fmaxf(mt0, __shfl_xor_sync(0xffffffffu, mt0, 1));
        mt0 = fmaxf(mt0, __shfl_xor_sync(0xffffffffu, mt0, 2));
        mt1 = fmaxf(mt1, __shfl_xor_sync(0xffffffffu, mt1, 1));
        mt1 = fmaxf(mt1, __shfl_xor_sync(0xffffffffu, mt1, 2));

        const float mn0 = fmaxf(m0, mt0);
        const float mn1 = fmaxf(m1, mt1);
        const float a0 = __expf(m0 - mn0);
        const float a1 = __expf(m1 - mn1);

        float ls0 = 0.f, ls1 = 0.f;
#pragma unroll
        for (int u = 0; u < 8; u++) {
            sacc[u][0] = __expf(sacc[u][0] - mn0);
            sacc[u][1] = __expf(sacc[u][1] - mn0);
            sacc[u][2] = __expf(sacc[u][2] - mn1);
            sacc[u][3] = __expf(sacc[u][3] - mn1);
            ls0 += sacc[u][0] + sacc[u][1];
            ls1 += sacc[u][2] + sacc[u][3];
        }
        ls0 += __shfl_xor_sync(0xffffffffu, ls0, 1);
        ls0 += __shfl_xor_sync(0xffffffffu, ls0, 2);
        ls1 += __shfl_xor_sync(0xffffffffu, ls1, 1);
        ls1 += __shfl_xor_sync(0xffffffffu, ls1, 2);
        l0 = l0 * a0 + ls0;  m0 = mn0;
        l1 = l1 * a1 + ls1;  m1 = mn1;

#pragma unroll
        for (int u = 0; u < 8; u++) {
            oacc[u][0] *= a0; oacc[u][1] *= a0;
            oacc[u][2] *= a1; oacc[u][3] *= a1;
        }

        // ---- stage next tile; prefetch kt+2 ----
        if (kt + 1 < NT) {
            stage((kt + 1) & 1);
            if (kt + 2 < NT) {
                const float* np = kbase + (size_t)(kt + 2) * 64 * QKV_N;
#pragma unroll
                for (int j = 0; j < 8; j++) {
                    rk[j] = *(const float4*)(np + j * 4);
                    rv[j] = *(const float4*)(np + DIM + j * 4);
                }
            }
        }

        // ---- pack P into fp16 A-frags (single) ----
        uint32_t pa[4][4];
#pragma unroll
        for (int t = 0; t < 4; t++) {
            pa[t][0] = pack2h(sacc[2 * t][0],     sacc[2 * t][1]);
            pa[t][1] = pack2h(sacc[2 * t][2],     sacc[2 * t][3]);
            pa[t][2] = pack2h(sacc[2 * t + 1][0], sacc[2 * t + 1][1]);
            pa[t][3] = pack2h(sacc[2 * t + 1][2], sacc[2 * t + 1][3]);
        }

        // ---- O += P @ V (single fp16 MMA per fragment) ----
#pragma unroll
        for (int t = 0; t < 4; t++) {
#pragma unroll
            for (int nd = 0; nd < 4; nd++) {
                uint32_t vf[4];
                uint32_t a = (uint32_t)(t * 16) * (KSTR * 2) + nd * 32 + offB;
                LDX4T(vf, uV + a);
                const int u = nd * 2;
                MMA_F16F32(oacc[u],     pa[t], vf[0], vf[2]);
                MMA_F16F32(oacc[u + 1], pa[t], vf[1], vf[3]);
            }
        }
        __syncthreads();
    }

    // ---- epilogue: O / l -> bf16 hi/lo for proj GEMM ----
    const float inv0 = 1.f / l0;
    const float inv1 = 1.f / l1;
    const int er = lane >> 2;
    const int ec = (lane & 3) * 2;
    const size_t tok0 = (size_t)b * SEQ + qt + w * 16 + er;
    const int colb = h * HD + ec;
#pragma unroll
    for (int u = 0; u < 8; u++) {
        const int col = colb + u * 8;
        uint32_t hp, lp;
        split_pair(oacc[u][0] * inv0, oacc[u][1] * inv0, hp, lp);
        *(uint32_t*)(oh + tok0 * DIM + col) = hp;
        *(uint32_t*)(ol + tok0 * DIM + col) = lp;
        split_pair(oacc[u][2] * inv1, oacc[u][3] * inv1, hp, lp);
        *(uint32_t*)(oh + (tok0 + 8) * DIM + col) = hp;
        *(uint32_t*)(ol + (tok0 + 8) * DIM + col) = lp;
    }
}

extern "C" void kernel_launch(void* const* d_in, const int* in_sizes, int n_in,
                              void* d_out, int out_size)
{
    const float* x      = (const float*)d_in[0];
    const float* qkv_w  = (const float*)d_in[1];
    const float* qkv_b  = (const float*)d_in[2];
    const float* proj_w = (const float*)d_in[3];
    const float* proj_b = (const float*)d_in[4];
    float* out = (float*)d_out;

    float* qkv;
    __nv_bfloat16 *xh, *xl, *qwh, *qwl, *pwh, *pwl, *ah, *al;
    cudaGetSymbolAddress((void**)&qkv, g_qkv);
    cudaGetSymbolAddress((void**)&xh,  g_xh);
    cudaGetSymbolAddress((void**)&xl,  g_xl);
    cudaGetSymbolAddress((void**)&qwh, g_qwh);
    cudaGetSymbolAddress((void**)&qwl, g_qwl);
    cudaGetSymbolAddress((void**)&pwh, g_pwh);
    cudaGetSymbolAddress((void**)&pwl, g_pwl);
    cudaGetSymbolAddress((void**)&ah,  g_ah);
    cudaGetSymbolAddress((void**)&al,  g_al);

    cudaFuncSetAttribute(gemm_bf16x3,
                         cudaFuncAttributeMaxDynamicSharedMemorySize, GEMM_SMEM);
    cudaFuncSetAttribute(attn_mma,
                         cudaFuncAttributeMaxDynamicSharedMemorySize, ATTN_SMEM);

    // splits
    const int nx = M_TOT * DIM, nqw = QKV_N * DIM, npw = DIM * DIM;
    split_kernel<<<(nx / 4 + 255) / 256, 256>>>(x, xh, xl, nx);
    split_kernel<<<(nqw / 4 + 255) / 256, 256>>>(qkv_w, qwh, qwl, nqw);
    split_kernel<<<(npw / 4 + 255) / 256, 256>>>(proj_w, pwh, pwl, npw);

    // QKV projection: [8192, 2304]
    gemm_bf16x3<<<dim3(QKV_N / 128, M_TOT / 128), 256, GEMM_SMEM>>>(
        xh, xl, qwh, qwl, qkv_b, qkv, QKV_N, DIM);

    // Attention (single-term fp16 tensor-core) -> bf16 hi/lo
    attn_mma<<<dim3(SEQ / 64, BATCH * NH), 128, ATTN_SMEM>>>(qkv, ah, al);

    // Output projection: [8192, 768]
    gemm_bf16x3<<<dim3(DIM / 128, M_TOT / 128), 256, GEMM_SMEM>>>(
        ah, al, pwh, pwl, proj_b, out, DIM, DIM);
}

// round 14
// speedup vs baseline: 1.8123x; 1.4969x over previous
#include <cuda_runtime.h>
#include <cuda_fp16.h>
#include <cstdint>

#define DIM   768
#define NH    12
#define HD    64
#define BATCH 8
#define SEQ   1024
#define M_TOT (BATCH * SEQ)   // 8192
#define QKV_N (3 * DIM)       // 2304

// Scratch (no allocation allowed in kernel_launch)
static __device__ float  g_qkv[(size_t)M_TOT * QKV_N];
static __device__ __half g_x16[(size_t)M_TOT * DIM];
static __device__ __half g_qw16[(size_t)QKV_N * DIM];
static __device__ __half g_pw16[(size_t)DIM * DIM];
static __device__ __half g_a16[(size_t)M_TOT * DIM];

// ---------------------------------------------------------------------------
// helpers
// ---------------------------------------------------------------------------
__device__ __forceinline__ uint32_t smem_u32(const void* p) {
    uint32_t a;
    asm("{ .reg .u64 t; cvta.to.shared.u64 t, %1; cvt.u32.u64 %0, t; }"
        : "=r"(a) : "l"(p));
    return a;
}
__device__ __forceinline__ uint32_t pack2h(float a, float b) {
    __half2 h = __floats2half2_rn(a, b);
    return *(uint32_t*)&h;
}

#define LDX4(r, addr)                                                        \
    asm volatile("ldmatrix.sync.aligned.m8n8.x4.shared.b16 {%0,%1,%2,%3}, [%4];" \
        : "=r"((r)[0]), "=r"((r)[1]), "=r"((r)[2]), "=r"((r)[3])             \
        : "r"(addr))

#define LDX4T(r, addr)                                                       \
    asm volatile("ldmatrix.sync.aligned.m8n8.x4.trans.shared.b16 {%0,%1,%2,%3}, [%4];" \
        : "=r"((r)[0]), "=r"((r)[1]), "=r"((r)[2]), "=r"((r)[3])             \
        : "r"(addr))

#define MMA_F16F32(c, a, b0, b1)                                             \
    asm volatile("mma.sync.aligned.m16n8k16.row.col.f32.f16.f16.f32 "        \
        "{%0,%1,%2,%3},{%4,%5,%6,%7},{%8,%9},{%0,%1,%2,%3};"                 \
        : "+f"((c)[0]), "+f"((c)[1]), "+f"((c)[2]), "+f"((c)[3])             \
        : "r"((a)[0]), "r"((a)[1]), "r"((a)[2]), "r"((a)[3]),                \
          "r"(b0), "r"(b1))

#define CP16(dst, src)                                                       \
    asm volatile("cp.async.ca.shared.global [%0], [%1], 16;"                 \
        :: "r"((uint32_t)(dst)), "l"(src))
#define CP_COMMIT()  asm volatile("cp.async.commit_group;" ::: "memory")
#define CP_WAIT(n)   asm volatile("cp.async.wait_group %0;" :: "n"(n) : "memory")

// ---------------------------------------------------------------------------
// f32 -> fp16 convert
// ---------------------------------------------------------------------------
__global__ void cvt_kernel(const float* __restrict__ in,
                           __half* __restrict__ h, int n)
{
    int i = (blockIdx.x * blockDim.x + threadIdx.x) * 4;
    if (i >= n) return;
    float4 v = *(const float4*)(in + i);
    *(uint2*)(h + i) = make_uint2(pack2h(v.x, v.y), pack2h(v.z, v.w));
}

// ---------------------------------------------------------------------------
// Single-term fp16 GEMM: C[M,N] = A[M,K] @ W[N,K]^T + bias (f32 out)
// 128x128 CTA, 256 thr, 8 warps of 64x32, cp.async double-buffered.
// ---------------------------------------------------------------------------
#define SB 40
#define ARR_B (128 * SB * 2)          // 10240 bytes
#define BUF_B (2 * ARR_B)             // A, B = 20480
#define GEMM_SMEM (2 * BUF_B)         // 40960

__global__ __launch_bounds__(256, 2) void gemm_f16(
    const __half* __restrict__ A, const __half* __restrict__ B,
    const float* __restrict__ bias, float* __restrict__ C, int N, int K)
{
    extern __shared__ __align__(16) char smraw[];
    const uint32_t sbase = smem_u32(smraw);

    const int tid  = threadIdx.x;
    const int wid  = tid >> 5;
    const int lane = tid & 31;
    const int wm   = wid & 1;
    const int wn   = wid >> 1;
    const int bm   = blockIdx.y * 128;
    const int bn   = blockIdx.x * 128;

    const uint32_t offA = (uint32_t)(lane & 15) * (SB * 2) + ((lane & 16) ? 16 : 0);
    const uint32_t offB = (uint32_t)(((lane & 16) >> 1) + (lane & 7)) * (SB * 2)
                        + ((lane & 8) ? 16 : 0);

    const int lrow = tid >> 1;
    const int cb   = (tid & 1) * 16;
    const __half* pA = A + (size_t)(bm + lrow) * K + cb;
    const __half* pB = B + (size_t)(bn + lrow) * K + cb;
    const uint32_t drow = (uint32_t)lrow * (SB * 2) + cb * 2;

    float acc[4][4][4];
#pragma unroll
    for (int t = 0; t < 4; t++)
#pragma unroll
        for (int u = 0; u < 4; u++)
#pragma unroll
            for (int j = 0; j < 4; j++) acc[t][u][j] = 0.f;

    const int nit = K / 32;

    auto issue = [&](int c) {
        const uint32_t ab = sbase + (uint32_t)((c & 1) * BUF_B) + drow;
        const int k0 = c * 32;
#pragma unroll
        for (int p = 0; p < 2; p++) {
            CP16(ab + p * 16,         pA + k0 + p * 8);
            CP16(ab + ARR_B + p * 16, pB + k0 + p * 8);
        }
        CP_COMMIT();
    };

    issue(0);

    for (int c = 0; c < nit; c++) {
        if (c + 1 < nit) { issue(c + 1); CP_WAIT(1); }
        else             { CP_WAIT(0); }
        __syncthreads();

        const uint32_t ab = sbase + (uint32_t)((c & 1) * BUF_B);
        const uint32_t uA = ab;
        const uint32_t uB = ab + ARR_B;

#pragma unroll
        for (int kk = 0; kk < 32; kk += 16) {
            uint32_t af[4][4], bf[2][4];
#pragma unroll
            for (int t = 0; t < 4; t++) {
                uint32_t base = (uint32_t)((wm * 64 + t * 16) * (SB * 2)) + kk * 2;
                LDX4(af[t], uA + base + offA);
            }
#pragma unroll
            for (int p = 0; p < 2; p++) {
                uint32_t base = (uint32_t)((wn * 32 + p * 16) * (SB * 2)) + kk * 2;
                LDX4(bf[p], uB + base + offB);
            }
#pragma unroll
            for (int t = 0; t < 4; t++) {
#pragma unroll
                for (int u = 0; u < 4; u++) {
                    const int p = u >> 1, o = (u & 1) * 2;
                    MMA_F16F32(acc[t][u], af[t], bf[p][o], bf[p][o + 1]);
                }
            }
        }
        __syncthreads();
    }

    const int er = lane >> 2;
    const int ec = (lane & 3) * 2;
#pragma unroll
    for (int t = 0; t < 4; t++) {
        const int row = bm + wm * 64 + t * 16 + er;
#pragma unroll
        for (int u = 0; u < 4; u++) {
            const int col = bn + wn * 32 + u * 8 + ec;
            const float b0 = bias[col], b1 = bias[col + 1];
            float2 v0 = {acc[t][u][0] + b0, acc[t][u][1] + b1};
            float2 v1 = {acc[t][u][2] + b0, acc[t][u][3] + b1};
            *(float2*)&C[(size_t)row * N + col]       = v0;
            *(float2*)&C[(size_t)(row + 8) * N + col] = v1;
        }
    }
}

// ---------------------------------------------------------------------------
// Tensor-core flash attention (round-13 core), epilogue -> plain fp16
// ---------------------------------------------------------------------------
#define KSTR 72
#define ASZ  (64 * KSTR * 2)
#define BUFSZ (2 * ASZ)
#define ATTN_SMEM (2 * BUFSZ)

__global__ __launch_bounds__(128) void attn_mma(const float* __restrict__ qkv,
                                                __half* __restrict__ oh)
{
    extern __shared__ __align__(16) char smraw[];
    const uint32_t sb = smem_u32(smraw);

    const int tid  = threadIdx.x;
    const int w    = tid >> 5;
    const int lane = tid & 31;
    const int qt   = blockIdx.x * 64;
    const int b    = blockIdx.y / NH;
    const int h    = blockIdx.y % NH;

    const float* base = qkv + (size_t)b * SEQ * QKV_N + h * HD;

    const uint32_t offA = (uint32_t)(lane & 15) * (KSTR * 2) + ((lane & 16) ? 16 : 0);
    const uint32_t offB = (uint32_t)(((lane & 16) >> 1) + (lane & 7)) * (KSTR * 2)
                        + ((lane & 8) ? 16 : 0);

    const int lr = tid >> 1;
    const int lc = (tid & 1) * 32;
    const uint32_t stoff = (uint32_t)lr * (KSTR * 2) + lc * 2;

    {
        const float* qp = base + (size_t)(qt + lr) * QKV_N + lc;
#pragma unroll
        for (int j = 0; j < 8; j++) {
            float4 v = *(const float4*)(qp + j * 4);
            *(uint2*)(smraw + stoff + j * 8) =
                make_uint2(pack2h(v.x * 0.125f, v.y * 0.125f),
                           pack2h(v.z * 0.125f, v.w * 0.125f));
        }
    }
    __syncthreads();

    uint32_t qf[4][4];
#pragma unroll
    for (int ks = 0; ks < 4; ks++) {
        uint32_t a = (uint32_t)(w * 16) * (KSTR * 2) + ks * 32 + offA;
        LDX4(qf[ks], sb + a);
    }
    __syncthreads();

    const float* kbase = base + DIM + (size_t)lr * QKV_N + lc;
    float4 rk[8], rv[8];
#pragma unroll
    for (int j = 0; j < 8; j++) {
        rk[j] = *(const float4*)(kbase + j * 4);
        rv[j] = *(const float4*)(kbase + DIM + j * 4);
    }

    auto stage = [&](int buf) {
        char* p = smraw + buf * BUFSZ + stoff;
#pragma unroll
        for (int j = 0; j < 8; j++) {
            *(uint2*)(p + j * 8) =
                make_uint2(pack2h(rk[j].x, rk[j].y), pack2h(rk[j].z, rk[j].w));
            *(uint2*)(p + ASZ + j * 8) =
                make_uint2(pack2h(rv[j].x, rv[j].y), pack2h(rv[j].z, rv[j].w));
        }
    };

    stage(0);
#pragma unroll
    for (int j = 0; j < 8; j++) {
        rk[j] = *(const float4*)(kbase + 64 * QKV_N + j * 4);
        rv[j] = *(const float4*)(kbase + 64 * QKV_N + DIM + j * 4);
    }
    __syncthreads();

    float oacc[8][4];
#pragma unroll
    for (int u = 0; u < 8; u++)
#pragma unroll
        for (int j = 0; j < 4; j++) oacc[u][j] = 0.f;
    float m0 = -1e30f, m1 = -1e30f, l0 = 0.f, l1 = 0.f;

    const int NT = SEQ / 64;
    for (int kt = 0; kt < NT; kt++) {
        const uint32_t bb = sb + (uint32_t)((kt & 1) * BUFSZ);
        const uint32_t uK = bb;
        const uint32_t uV = bb + ASZ;

        float sacc[8][4];
#pragma unroll
        for (int u = 0; u < 8; u++)
#pragma unroll
            for (int j = 0; j < 4; j++) sacc[u][j] = 0.f;

#pragma unroll
        for (int ks = 0; ks < 4; ks++) {
#pragma unroll
            for (int np = 0; np < 4; np++) {
                uint32_t kf[4];
                uint32_t a = (uint32_t)(np * 16) * (KSTR * 2) + ks * 32 + offB;
                LDX4(kf, uK + a);
                const int u = np * 2;
                MMA_F16F32(sacc[u],     qf[ks], kf[0], kf[1]);
                MMA_F16F32(sacc[u + 1], qf[ks], kf[2], kf[3]);
            }
        }

        float mt0 = -1e30f, mt1 = -1e30f;
#pragma unroll
        for (int u = 0; u < 8; u++) {
            mt0 = fmaxf(mt0, fmaxf(sacc[u][0], sacc[u][1]));
            mt1 = fmaxf(mt1, fmaxf(sacc[u][2], sacc[u][3]));
        }
        mt0 = fmaxf(mt0, __shfl_xor_sync(0xffffffffu, mt0, 1));
        mt0 = fmaxf(mt0, __shfl_xor_sync(0xffffffffu, mt0, 2));
        mt1 = fmaxf(mt1, __shfl_xor_sync(0xffffffffu, mt1, 1));
        mt1 = fmaxf(mt1, __shfl_xor_sync(0xffffffffu, mt1, 2));

        const float mn0 = fmaxf(m0, mt0);
        const float mn1 = fmaxf(m1, mt1);
        const float a0 = __expf(m0 - mn0);
        const float a1 = __expf(m1 - mn1);

        float ls0 = 0.f, ls1 = 0.f;
#pragma unroll
        for (int u = 0; u < 8; u++) {
            sacc[u][0] = __expf(sacc[u][0] - mn0);
            sacc[u][1] = __expf(sacc[u][1] - mn0);
            sacc[u][2] = __expf(sacc[u][2] - mn1);
            sacc[u][3] = __expf(sacc[u][3] - mn1);
            ls0 += sacc[u][0] + sacc[u][1];
            ls1 += sacc[u][2] + sacc[u][3];
        }
        ls0 += __shfl_xor_sync(0xffffffffu, ls0, 1);
        ls0 += __shfl_xor_sync(0xffffffffu, ls0, 2);
        ls1 += __shfl_xor_sync(0xffffffffu, ls1, 1);
        ls1 += __shfl_xor_sync(0xffffffffu, ls1, 2);
        l0 = l0 * a0 + ls0;  m0 = mn0;
        l1 = l1 * a1 + ls1;  m1 = mn1;

#pragma unroll
        for (int u = 0; u < 8; u++) {
            oacc[u][0] *= a0; oacc[u][1] *= a0;
            oacc[u][2] *= a1; oacc[u][3] *= a1;
        }

        if (kt + 1 < NT) {
            stage((kt + 1) & 1);
            if (kt + 2 < NT) {
                const float* np = kbase + (size_t)(kt + 2) * 64 * QKV_N;
#pragma unroll
                for (int j = 0; j < 8; j++) {
                    rk[j] = *(const float4*)(np + j * 4);
                    rv[j] = *(const float4*)(np + DIM + j * 4);
                }
            }
        }

        uint32_t pa[4][4];
#pragma unroll
        for (int t = 0; t < 4; t++) {
            pa[t][0] = pack2h(sacc[2 * t][0],     sacc[2 * t][1]);
            pa[t][1] = pack2h(sacc[2 * t][2],     sacc[2 * t][3]);
            pa[t][2] = pack2h(sacc[2 * t + 1][0], sacc[2 * t + 1][1]);
            pa[t][3] = pack2h(sacc[2 * t + 1][2], sacc[2 * t + 1][3]);
        }

#pragma unroll
        for (int t = 0; t < 4; t++) {
#pragma unroll
            for (int nd = 0; nd < 4; nd++) {
                uint32_t vf[4];
                uint32_t a = (uint32_t)(t * 16) * (KSTR * 2) + nd * 32 + offB;
                LDX4T(vf, uV + a);
                const int u = nd * 2;
                MMA_F16F32(oacc[u],     pa[t], vf[0], vf[2]);
                MMA_F16F32(oacc[u + 1], pa[t], vf[1], vf[3]);
            }
        }
        __syncthreads();
    }

    // epilogue -> fp16 for proj GEMM
    const float inv0 = 1.f / l0;
    const float inv1 = 1.f / l1;
    const int er = lane >> 2;
    const int ec = (lane & 3) * 2;
    const size_t tok0 = (size_t)b * SEQ + qt + w * 16 + er;
    const int colb = h * HD + ec;
#pragma unroll
    for (int u = 0; u < 8; u++) {
        const int col = colb + u * 8;
        *(uint32_t*)(oh + tok0 * DIM + col) =
            pack2h(oacc[u][0] * inv0, oacc[u][1] * inv0);
        *(uint32_t*)(oh + (tok0 + 8) * DIM + col) =
            pack2h(oacc[u][2] * inv1, oacc[u][3] * inv1);
    }
}

extern "C" void kernel_launch(void* const* d_in, const int* in_sizes, int n_in,
                              void* d_out, int out_size)
{
    const float* x      = (const float*)d_in[0];
    const float* qkv_w  = (const float*)d_in[1];
    const float* qkv_b  = (const float*)d_in[2];
    const float* proj_w = (const float*)d_in[3];
    const float* proj_b = (const float*)d_in[4];
    float* out = (float*)d_out;

    float* qkv;
    __half *x16, *qw16, *pw16, *a16;
    cudaGetSymbolAddress((void**)&qkv,  g_qkv);
    cudaGetSymbolAddress((void**)&x16,  g_x16);
    cudaGetSymbolAddress((void**)&qw16, g_qw16);
    cudaGetSymbolAddress((void**)&pw16, g_pw16);
    cudaGetSymbolAddress((void**)&a16,  g_a16);

    cudaFuncSetAttribute(gemm_f16,
                         cudaFuncAttributeMaxDynamicSharedMemorySize, GEMM_SMEM);
    cudaFuncSetAttribute(attn_mma,
                         cudaFuncAttributeMaxDynamicSharedMemorySize, ATTN_SMEM);

    // converts
    const int nx = M_TOT * DIM, nqw = QKV_N * DIM, npw = DIM * DIM;
    cvt_kernel<<<(nx / 4 + 255) / 256, 256>>>(x, x16, nx);
    cvt_kernel<<<(nqw / 4 + 255) / 256, 256>>>(qkv_w, qw16, nqw);
    cvt_kernel<<<(npw / 4 + 255) / 256, 256>>>(proj_w, pw16, npw);

    // QKV projection: [8192, 2304]
    gemm_f16<<<dim3(QKV_N / 128, M_TOT / 128), 256, GEMM_SMEM>>>(
        x16, qw16, qkv_b, qkv, QKV_N, DIM);

    // Attention (single-term fp16 tensor-core) -> fp16
    attn_mma<<<dim3(SEQ / 64, BATCH * NH), 128, ATTN_SMEM>>>(qkv, a16);

    // Output projection: [8192, 768]
    gemm_f16<<<dim3(DIM / 128, M_TOT / 128), 256, GEMM_SMEM>>>(
        a16, pw16, proj_b, out, DIM, DIM);
}

// round 15
// speedup vs baseline: 2.6260x; 1.4490x over previous
#include <cuda_runtime.h>
#include <cuda_fp16.h>
#include <cstdint>

#define DIM   768
#define NH    12
#define HD    64
#define BATCH 8
#define SEQ   1024
#define M_TOT (BATCH * SEQ)   // 8192
#define QKV_N (3 * DIM)       // 2304

// Q pre-scale: 0.125 * log2(e)  (softmax done in exp2 domain)
#define QSCALE 0.18033688f

// Scratch (no allocation allowed in kernel_launch)
static __device__ __half g_qkv16[(size_t)M_TOT * QKV_N];
static __device__ __half g_x16[(size_t)M_TOT * DIM];
static __device__ __half g_qw16[(size_t)QKV_N * DIM];
static __device__ __half g_pw16[(size_t)DIM * DIM];
static __device__ __half g_a16[(size_t)M_TOT * DIM];

// ---------------------------------------------------------------------------
// helpers
// ---------------------------------------------------------------------------
__device__ __forceinline__ uint32_t smem_u32(const void* p) {
    uint32_t a;
    asm("{ .reg .u64 t; cvta.to.shared.u64 t, %1; cvt.u32.u64 %0, t; }"
        : "=r"(a) : "l"(p));
    return a;
}
__device__ __forceinline__ uint32_t pack2h(float a, float b) {
    __half2 h = __floats2half2_rn(a, b);
    return *(uint32_t*)&h;
}
__device__ __forceinline__ float ex2(float x) {
    float r;
    asm("ex2.approx.f32 %0, %1;" : "=f"(r) : "f"(x));
    return r;
}

#define LDX4(r, addr)                                                        \
    asm volatile("ldmatrix.sync.aligned.m8n8.x4.shared.b16 {%0,%1,%2,%3}, [%4];" \
        : "=r"((r)[0]), "=r"((r)[1]), "=r"((r)[2]), "=r"((r)[3])             \
        : "r"(addr))

#define LDX4T(r, addr)                                                       \
    asm volatile("ldmatrix.sync.aligned.m8n8.x4.trans.shared.b16 {%0,%1,%2,%3}, [%4];" \
        : "=r"((r)[0]), "=r"((r)[1]), "=r"((r)[2]), "=r"((r)[3])             \
        : "r"(addr))

#define MMA_F16F32(c, a, b0, b1)                                             \
    asm volatile("mma.sync.aligned.m16n8k16.row.col.f32.f16.f16.f32 "        \
        "{%0,%1,%2,%3},{%4,%5,%6,%7},{%8,%9},{%0,%1,%2,%3};"                 \
        : "+f"((c)[0]), "+f"((c)[1]), "+f"((c)[2]), "+f"((c)[3])             \
        : "r"((a)[0]), "r"((a)[1]), "r"((a)[2]), "r"((a)[3]),                \
          "r"(b0), "r"(b1))

#define CP16(dst, src)                                                       \
    asm volatile("cp.async.ca.shared.global [%0], [%1], 16;"                 \
        :: "r"((uint32_t)(dst)), "l"(src))
#define CP_COMMIT()  asm volatile("cp.async.commit_group;" ::: "memory")
#define CP_WAIT(n)   asm volatile("cp.async.wait_group %0;" :: "n"(n) : "memory")

// ---------------------------------------------------------------------------
// f32 -> fp16 convert
// ---------------------------------------------------------------------------
__global__ void cvt_kernel(const float* __restrict__ in,
                           __half* __restrict__ h, int n)
{
    int i = (blockIdx.x * blockDim.x + threadIdx.x) * 4;
    if (i >= n) return;
    float4 v = *(const float4*)(in + i);
    *(uint2*)(h + i) = make_uint2(pack2h(v.x, v.y), pack2h(v.z, v.w));
}

// ---------------------------------------------------------------------------
// Single-term fp16 GEMM: C[M,N] = A[M,K] @ W[N,K]^T + bias
// MODE 0: f32 out.  MODE 1: fp16 out, columns < DIM scaled by QSCALE.
// 128x128 CTA, 256 thr, 8 warps of 64x32, cp.async double-buffered.
// ---------------------------------------------------------------------------
#define SB 40
#define ARR_B (128 * SB * 2)
#define BUF_B (2 * ARR_B)
#define GEMM_SMEM (2 * BUF_B)

template <int MODE>
__global__ __launch_bounds__(256, 2) void gemm_f16(
    const __half* __restrict__ A, const __half* __restrict__ B,
    const float* __restrict__ bias, float* __restrict__ C,
    __half* __restrict__ C16, int N, int K)
{
    extern __shared__ __align__(16) char smraw[];
    const uint32_t sbase = smem_u32(smraw);

    const int tid  = threadIdx.x;
    const int wid  = tid >> 5;
    const int lane = tid & 31;
    const int wm   = wid & 1;
    const int wn   = wid >> 1;
    const int bm   = blockIdx.y * 128;
    const int bn   = blockIdx.x * 128;

    const uint32_t offA = (uint32_t)(lane & 15) * (SB * 2) + ((lane & 16) ? 16 : 0);
    const uint32_t offB = (uint32_t)(((lane & 16) >> 1) + (lane & 7)) * (SB * 2)
                        + ((lane & 8) ? 16 : 0);

    const int lrow = tid >> 1;
    const int cb   = (tid & 1) * 16;
    const __half* pA = A + (size_t)(bm + lrow) * K + cb;
    const __half* pB = B + (size_t)(bn + lrow) * K + cb;
    const uint32_t drow = (uint32_t)lrow * (SB * 2) + cb * 2;

    float acc[4][4][4];
#pragma unroll
    for (int t = 0; t < 4; t++)
#pragma unroll
        for (int u = 0; u < 4; u++)
#pragma unroll
            for (int j = 0; j < 4; j++) acc[t][u][j] = 0.f;

    const int nit = K / 32;

    auto issue = [&](int c) {
        const uint32_t ab = sbase + (uint32_t)((c & 1) * BUF_B) + drow;
        const int k0 = c * 32;
#pragma unroll
        for (int p = 0; p < 2; p++) {
            CP16(ab + p * 16,         pA + k0 + p * 8);
            CP16(ab + ARR_B + p * 16, pB + k0 + p * 8);
        }
        CP_COMMIT();
    };

    issue(0);

    for (int c = 0; c < nit; c++) {
        if (c + 1 < nit) { issue(c + 1); CP_WAIT(1); }
        else             { CP_WAIT(0); }
        __syncthreads();

        const uint32_t ab = sbase + (uint32_t)((c & 1) * BUF_B);
        const uint32_t uA = ab;
        const uint32_t uB = ab + ARR_B;

#pragma unroll
        for (int kk = 0; kk < 32; kk += 16) {
            uint32_t af[4][4], bf[2][4];
#pragma unroll
            for (int t = 0; t < 4; t++) {
                uint32_t base = (uint32_t)((wm * 64 + t * 16) * (SB * 2)) + kk * 2;
                LDX4(af[t], uA + base + offA);
            }
#pragma unroll
            for (int p = 0; p < 2; p++) {
                uint32_t base = (uint32_t)((wn * 32 + p * 16) * (SB * 2)) + kk * 2;
                LDX4(bf[p], uB + base + offB);
            }
#pragma unroll
            for (int t = 0; t < 4; t++) {
#pragma unroll
                for (int u = 0; u < 4; u++) {
                    const int p = u >> 1, o = (u & 1) * 2;
                    MMA_F16F32(acc[t][u], af[t], bf[p][o], bf[p][o + 1]);
                }
            }
        }
        __syncthreads();
    }

    const int er = lane >> 2;
    const int ec = (lane & 3) * 2;
#pragma unroll
    for (int t = 0; t < 4; t++) {
        const int row = bm + wm * 64 + t * 16 + er;
#pragma unroll
        for (int u = 0; u < 4; u++) {
            const int col = bn + wn * 32 + u * 8 + ec;
            const float b0 = bias[col], b1 = bias[col + 1];
            if (MODE == 0) {
                float2 v0 = {acc[t][u][0] + b0, acc[t][u][1] + b1};
                float2 v1 = {acc[t][u][2] + b0, acc[t][u][3] + b1};
                *(float2*)&C[(size_t)row * N + col]       = v0;
                *(float2*)&C[(size_t)(row + 8) * N + col] = v1;
            } else {
                const float sc = (col < DIM) ? QSCALE : 1.f;
                *(uint32_t*)&C16[(size_t)row * N + col] =
                    pack2h((acc[t][u][0] + b0) * sc, (acc[t][u][1] + b1) * sc);
                *(uint32_t*)&C16[(size_t)(row + 8) * N + col] =
                    pack2h((acc[t][u][2] + b0) * sc, (acc[t][u][3] + b1) * sc);
            }
        }
    }
}

// ---------------------------------------------------------------------------
// Tensor-core flash attention v6: fp16 Q/K/V via cp.async (3-stage K/V ring),
// exp2-domain softmax (Q pre-scaled by QSCALE in the QKV GEMM epilogue).
// 128 thr, 64 q-rows/CTA.
// ---------------------------------------------------------------------------
#define KSTR 72
#define ASZ  (64 * KSTR * 2)          // 9216 bytes (64 rows x 144B)
#define BUFSZ (2 * ASZ)               // K,V per stage = 18432
#define NSTAGE 3
#define ATTN_SMEM (ASZ + NSTAGE * BUFSZ)   // 9216 + 55296 = 64512

__global__ __launch_bounds__(128) void attn_mma(const __half* __restrict__ qkv,
                                                __half* __restrict__ oh)
{
    extern __shared__ __align__(16) char smraw[];
    const uint32_t sb = smem_u32(smraw);

    const int tid  = threadIdx.x;
    const int w    = tid >> 5;
    const int lane = tid & 31;
    const int qt   = blockIdx.x * 64;
    const int b    = blockIdx.y / NH;
    const int h    = blockIdx.y % NH;

    const __half* base = qkv + (size_t)b * SEQ * QKV_N + h * HD;

    const uint32_t offA = (uint32_t)(lane & 15) * (KSTR * 2) + ((lane & 16) ? 16 : 0);
    const uint32_t offB = (uint32_t)(((lane & 16) >> 1) + (lane & 7)) * (KSTR * 2)
                        + ((lane & 8) ? 16 : 0);

    // staging mapping: row = tid/2 (0..63), half = (tid&1) -> 64B (4x16B)
    const int lr = tid >> 1;
    const int lc = (tid & 1) * 32;                                // elem offset
    const uint32_t stoff = (uint32_t)lr * (KSTR * 2) + lc * 2;    // byte offset

    const int NT = SEQ / 64;

    // ---- issue Q (group), then K/V tiles 0..2 (3 groups) ----
    {
        const __half* qp = base + (size_t)(qt + lr) * QKV_N + lc;
#pragma unroll
        for (int p = 0; p < 4; p++)
            CP16(sb + stoff + p * 16, qp + p * 8);
        CP_COMMIT();
    }
    const __half* kbase = base + DIM + (size_t)lr * QKV_N + lc;
    auto issueKV = [&](int kt) {
        const uint32_t db = sb + ASZ + (uint32_t)((kt % NSTAGE) * BUFSZ) + stoff;
        const __half* so = kbase + (size_t)kt * 64 * QKV_N;
#pragma unroll
        for (int p = 0; p < 4; p++) {
            CP16(db + p * 16,       so + p * 8);          // K
            CP16(db + ASZ + p * 16, so + DIM + p * 8);    // V
        }
        CP_COMMIT();
    };
    issueKV(0); issueKV(1); issueKV(2);

    // ---- wait Q, pull A-frags ----
    CP_WAIT(3);
    __syncthreads();
    uint32_t qf[4][4];
#pragma unroll
    for (int ks = 0; ks < 4; ks++) {
        uint32_t a = (uint32_t)(w * 16) * (KSTR * 2) + ks * 32 + offA;
        LDX4(qf[ks], sb + a);
    }

    float oacc[8][4];
#pragma unroll
    for (int u = 0; u < 8; u++)
#pragma unroll
        for (int j = 0; j < 4; j++) oacc[u][j] = 0.f;
    float m0 = -1e30f, m1 = -1e30f, l0 = 0.f, l1 = 0.f;

    for (int kt = 0; kt < NT; kt++) {
        if (kt + 2 < NT)      { CP_WAIT(2); }
        else if (kt + 1 < NT) { CP_WAIT(1); }
        else                  { CP_WAIT(0); }
        __syncthreads();

        const uint32_t bb = sb + ASZ + (uint32_t)((kt % NSTAGE) * BUFSZ);
        const uint32_t uK = bb;
        const uint32_t uV = bb + ASZ;

        // ---- S = Q @ K^T (values already in log2 scale via QSCALE) ----
        float sacc[8][4];
#pragma unroll
        for (int u = 0; u < 8; u++)
#pragma unroll
            for (int j = 0; j < 4; j++) sacc[u][j] = 0.f;

#pragma unroll
        for (int ks = 0; ks < 4; ks++) {
#pragma unroll
            for (int np = 0; np < 4; np++) {
                uint32_t kf[4];
                uint32_t a = (uint32_t)(np * 16) * (KSTR * 2) + ks * 32 + offB;
                LDX4(kf, uK + a);
                const int u = np * 2;
                MMA_F16F32(sacc[u],     qf[ks], kf[0], kf[1]);
                MMA_F16F32(sacc[u + 1], qf[ks], kf[2], kf[3]);
            }
        }

        // ---- online softmax in exp2 domain ----
        float mt0 = -1e30f, mt1 = -1e30f;
#pragma unroll
        for (int u = 0; u < 8; u++) {
            mt0 = fmaxf(mt0, fmaxf(sacc[u][0], sacc[u][1]));
            mt1 = fmaxf(mt1, fmaxf(sacc[u][2], sacc[u][3]));
        }
        mt0 = fmaxf(mt0, __shfl_xor_sync(0xffffffffu, mt0, 1));
        mt0 = fmaxf(mt0, __shfl_xor_sync(0xffffffffu, mt0, 2));
        mt1 = fmaxf(mt1, __shfl_xor_sync(0xffffffffu, mt1, 1));
        mt1 = fmaxf(mt1, __shfl_xor_sync(0xffffffffu, mt1, 2));

        const float mn0 = fmaxf(m0, mt0);
        const float mn1 = fmaxf(m1, mt1);
        const float a0 = ex2(m0 - mn0);
        const float a1 = ex2(m1 - mn1);

        float ls0 = 0.f, ls1 = 0.f;
#pragma unroll
        for (int u = 0; u < 8; u++) {
            sacc[u][0] = ex2(sacc[u][0] - mn0);
            sacc[u][1] = ex2(sacc[u][1] - mn0);
            sacc[u][2] = ex2(sacc[u][2] - mn1);
            sacc[u][3] = ex2(sacc[u][3] - mn1);
            ls0 += sacc[u][0] + sacc[u][1];
            ls1 += sacc[u][2] + sacc[u][3];
        }
        ls0 += __shfl_xor_sync(0xffffffffu, ls0, 1);
        ls0 += __shfl_xor_sync(0xffffffffu, ls0, 2);
        ls1 += __shfl_xor_sync(0xffffffffu, ls1, 1);
        ls1 += __shfl_xor_sync(0xffffffffu, ls1, 2);
        l0 = l0 * a0 + ls0;  m0 = mn0;
        l1 = l1 * a1 + ls1;  m1 = mn1;

#pragma unroll
        for (int u = 0; u < 8; u++) {
            oacc[u][0] *= a0; oacc[u][1] *= a0;
            oacc[u][2] *= a1; oacc[u][3] *= a1;
        }

        // ---- pack P into fp16 A-frags ----
        uint32_t pa[4][4];
#pragma unroll
        for (int t = 0; t < 4; t++) {
            pa[t][0] = pack2h(sacc[2 * t][0],     sacc[2 * t][1]);
            pa[t][1] = pack2h(sacc[2 * t][2],     sacc[2 * t][3]);
            pa[t][2] = pack2h(sacc[2 * t + 1][0], sacc[2 * t + 1][1]);
            pa[t][3] = pack2h(sacc[2 * t + 1][2], sacc[2 * t + 1][3]);
        }

        // ---- O += P @ V ----
#pragma unroll
        for (int t = 0; t < 4; t++) {
#pragma unroll
            for (int nd = 0; nd < 4; nd++) {
                uint32_t vf[4];
                uint32_t a = (uint32_t)(t * 16) * (KSTR * 2) + nd * 32 + offB;
                LDX4T(vf, uV + a);
                const int u = nd * 2;
                MMA_F16F32(oacc[u],     pa[t], vf[0], vf[2]);
                MMA_F16F32(oacc[u + 1], pa[t], vf[1], vf[3]);
            }
        }
        __syncthreads();   // all reads of buffer kt%NSTAGE done

        if (kt + 3 < NT) issueKV(kt + 3);
    }

    // ---- epilogue -> fp16 for proj GEMM ----
    const float inv0 = 1.f / l0;
    const float inv1 = 1.f / l1;
    const int er = lane >> 2;
    const int ec = (lane & 3) * 2;
    const size_t tok0 = (size_t)b * SEQ + qt + w * 16 + er;
    const int colb = h * HD + ec;
#pragma unroll
    for (int u = 0; u < 8; u++) {
        const int col = colb + u * 8;
        *(uint32_t*)(oh + tok0 * DIM + col) =
            pack2h(oacc[u][0] * inv0, oacc[u][1] * inv0);
        *(uint32_t*)(oh + (tok0 + 8) * DIM + col) =
            pack2h(oacc[u][2] * inv1, oacc[u][3] * inv1);
    }
}

extern "C" void kernel_launch(void* const* d_in, const int* in_sizes, int n_in,
                              void* d_out, int out_size)
{
    const float* x      = (const float*)d_in[0];
    const float* qkv_w  = (const float*)d_in[1];
    const float* qkv_b  = (const float*)d_in[2];
    const float* proj_w = (const float*)d_in[3];
    const float* proj_b = (const float*)d_in[4];
    float* out = (float*)d_out;

    __half *qkv16, *x16, *qw16, *pw16, *a16;
    cudaGetSymbolAddress((void**)&qkv16, g_qkv16);
    cudaGetSymbolAddress((void**)&x16,   g_x16);
    cudaGetSymbolAddress((void**)&qw16,  g_qw16);
    cudaGetSymbolAddress((void**)&pw16,  g_pw16);
    cudaGetSymbolAddress((void**)&a16,   g_a16);

    cudaFuncSetAttribute(gemm_f16<0>,
                         cudaFuncAttributeMaxDynamicSharedMemorySize, GEMM_SMEM);
    cudaFuncSetAttribute(gemm_f16<1>,
                         cudaFuncAttributeMaxDynamicSharedMemorySize, GEMM_SMEM);
    cudaFuncSetAttribute(attn_mma,
                         cudaFuncAttributeMaxDynamicSharedMemorySize, ATTN_SMEM);

    // converts
    const int nx = M_TOT * DIM, nqw = QKV_N * DIM, npw = DIM * DIM;
    cvt_kernel<<<(nx / 4 + 255) / 256, 256>>>(x, x16, nx);
    cvt_kernel<<<(nqw / 4 + 255) / 256, 256>>>(qkv_w, qw16, nqw);
    cvt_kernel<<<(npw / 4 + 255) / 256, 256>>>(proj_w, pw16, npw);

    // QKV projection -> fp16 (Q columns pre-scaled)
    gemm_f16<1><<<dim3(QKV_N / 128, M_TOT / 128), 256, GEMM_SMEM>>>(
        x16, qw16, qkv_b, nullptr, qkv16, QKV_N, DIM);

    // Attention (single-term fp16, cp.async ring) -> fp16
    attn_mma<<<dim3(SEQ / 64, BATCH * NH), 128, ATTN_SMEM>>>(qkv16, a16);

    // Output projection -> f32
    gemm_f16<0><<<dim3(DIM / 128, M_TOT / 128), 256, GEMM_SMEM>>>(
        a16, pw16, proj_b, out, nullptr, DIM, DIM);
}